// round 15
// baseline (speedup 1.0000x reference)
#include <cuda_runtime.h>
#include <cuda_fp16.h>
#include <cstdint>

#define DINLINE __device__ __forceinline__

// ---------------- problem constants ----------------
#define ROWS_TOTAL 32768      // B*N = 8*4096
#define CDIM 768
#define KDIM 384              // radix-2 half transform
#define NB 8
#define INV_NTOT (1.0f/25165824.0f)   // 1 / (B*H*W*C)
#define LAMBDA 0.01f

// ---------------- device scratch ----------------
__device__ __half g_cas384[KDIM * KDIM];               // symmetric 384-pt cas
__device__ float2 g_tw[CDIM];                          // (cos, sin)(2πk/768)
__device__ __half g_Xh[(size_t)ROWS_TOTAL * CDIM];     // [r][xe(384)|xo(384)]
__device__ __half g_Y[(size_t)ROWS_TOTAL * CDIM];      // interleaved Y (MLP input)
__device__ __half g_D[(size_t)ROWS_TOTAL * CDIM];      // [r][De(384)|Do(384)]
__device__ __half g_W1T[NB * 192 * 96];
__device__ __half g_W2T[NB * 192 * 192];

// ---------------- asm helpers ----------------
DINLINE void ldsm4(uint32_t& r0, uint32_t& r1, uint32_t& r2, uint32_t& r3, const void* p) {
    uint32_t a = (uint32_t)__cvta_generic_to_shared(p);
    asm volatile("ldmatrix.sync.aligned.m8n8.x4.shared.b16 {%0,%1,%2,%3}, [%4];"
                 : "=r"(r0), "=r"(r1), "=r"(r2), "=r"(r3) : "r"(a));
}
DINLINE void mma_h(uint32_t& c0, uint32_t& c1, const uint32_t* a, const uint32_t* b) {
    asm volatile("mma.sync.aligned.m16n8k16.row.col.f16.f16.f16.f16 "
                 "{%0,%1}, {%2,%3,%4,%5}, {%6,%7}, {%0,%1};"
                 : "+r"(c0), "+r"(c1)
                 : "r"(a[0]), "r"(a[1]), "r"(a[2]), "r"(a[3]),
                   "r"(b[0]), "r"(b[1]));
}
DINLINE void cpa16(void* smem, const void* g) {
    uint32_t a = (uint32_t)__cvta_generic_to_shared(smem);
    asm volatile("cp.async.cg.shared.global [%0], [%1], 16;" :: "r"(a), "l"(g));
}
DINLINE void cp_commit() { asm volatile("cp.async.commit_group;"); }
template<int N> DINLINE void cp_wait() { asm volatile("cp.async.wait_group %0;" :: "n"(N)); }

// ---------------- fused prep kernel ----------------
constexpr int PX_BLOCKS  = 24576;   // 6,291,456 float4 / 256
constexpr int PCAS_BLOCKS = 576;    // 384*384 / 256
constexpr int PW1_BLOCKS = 576;
constexpr int PW2_BLOCKS = 1152;
constexpr int PREP_BLOCKS = PX_BLOCKS + PCAS_BLOCKS + 1 + PW1_BLOCKS + PW2_BLOCKS;

__global__ void prep_all(const float* __restrict__ x,
                         const float* __restrict__ w1,
                         const float* __restrict__ w2) {
    int bid = blockIdx.x, tid = threadIdx.x;
    if (bid < PX_BLOCKS) {
        size_t i = ((size_t)bid * 256 + tid) * 4;
        float4 v = *(const float4*)&x[i];
        size_t r = i / CDIM;
        int c = (int)(i % CDIM);
        int m = c >> 1;
        __half2 he, hoo;
        he.x = __float2half(v.x);  he.y = __float2half(v.z);
        hoo.x = __float2half(v.y); hoo.y = __float2half(v.w);
        *(__half2*)&g_Xh[r * CDIM + m]        = he;
        *(__half2*)&g_Xh[r * CDIM + 384 + m]  = hoo;
    } else if (bid < PX_BLOCKS + PCAS_BLOCKS) {
        int idx = (bid - PX_BLOCKS) * 256 + tid;
        int i = idx / KDIM, j = idx % KDIM;
        int p = (int)(((long long)i * (long long)j) % KDIM);
        float ang = (float)p * (6.28318530717958647692f / (float)KDIM);
        g_cas384[idx] = __float2half(cosf(ang) + sinf(ang));
    } else if (bid == PX_BLOCKS + PCAS_BLOCKS) {
#pragma unroll
        for (int q = 0; q < 3; q++) {
            int k = tid + q * 256;
            float ang = (float)k * (6.28318530717958647692f / (float)CDIM);
            g_tw[k] = make_float2(cosf(ang), sinf(ang));
        }
    } else if (bid < PX_BLOCKS + PCAS_BLOCKS + 1 + PW1_BLOCKS) {
        int idx = (bid - PX_BLOCKS - PCAS_BLOCKS - 1) * 256 + tid;
        int i = idx % 96;
        int n = (idx / 96) % 192;
        int k = idx / (96 * 192);
        float v = (n < 96) ? w1[((0 * NB + k) * 96 + i) * 96 + n]
                           : w1[((1 * NB + k) * 96 + i) * 96 + (n - 96)];
        g_W1T[idx] = __float2half(v);
    } else {
        int idx = (bid - PX_BLOCKS - PCAS_BLOCKS - 1 - PW1_BLOCKS) * 256 + tid;
        int j = idx % 192;
        int c = (idx / 192) % 192;
        int k = idx / (192 * 192);
        float v;
        if (c < 96) {
            v = (j < 96) ?  w2[((0 * NB + k) * 96 + j) * 96 + c]
                         : -w2[((1 * NB + k) * 96 + (j - 96)) * 96 + c];
        } else {
            int cc = c - 96;
            v = (j < 96) ?  w2[((1 * NB + k) * 96 + j) * 96 + cc]
                         :  w2[((0 * NB + k) * 96 + (j - 96)) * 96 + cc];
        }
        g_W2T[idx] = __float2half(v);
    }
}

// ---------------- fused GEMM+combine: tile 128x384, 512 threads, 2 CTAs/SM ----------------
// A = g_Xh or g_D viewed as [65536, 384]; B = cas384 (full N). Epilogue exchanges
// accumulators through SMEM and performs the radix-2 combine inline.
constexpr int G_BK = 32;
constexpr int G_STAGE_ELEMS = (128 + 384) * 32;        // 16384 halves = 32KB
constexpr int G_EX_STRIDE = 392;                       // exchange stride (halves)
constexpr int G_SMEM_BYTES = 128 * G_EX_STRIDE * 2 > 3 * G_STAGE_ELEMS * 2
                           ? 128 * G_EX_STRIDE * 2 : 3 * G_STAGE_ELEMS * 2;  // 100352
constexpr int G_NIT = KDIM / G_BK;                     // 12

DINLINE uint32_t g_off(int r, int chunk) {
    return (uint32_t)(r * 32 + ((chunk ^ ((r >> 1) & 3)) << 3));
}

DINLINE void g_fill(__half* sh, int s, int k0,
                    const __half* __restrict__ Ag,
                    size_t m0, int tid) {
    __half* As = sh + s * G_STAGE_ELEMS;
    __half* Bs = As + 128 * 32;
    {   // A: 128 rows x 4 chunks = 512, one per thread
        int r = tid >> 2, c = tid & 3;
        cpa16(&As[g_off(r, c)], &Ag[(m0 + r) * KDIM + k0 + c * 8]);
    }
#pragma unroll
    for (int i = 0; i < 3; i++) {     // B: 384 rows x 4 chunks = 1536
        int e = tid + i * 512;
        int r = e >> 2, c = e & 3;
        cpa16(&Bs[g_off(r, c)], &g_cas384[(size_t)r * KDIM + k0 + c * 8]);
    }
}

template<int MODE>
__global__ void __launch_bounds__(512, 2) gemm_comb(const float* __restrict__ xbias,
                                                    float* __restrict__ outp) {
    extern __shared__ __half sh[];
    const size_t m0 = (size_t)blockIdx.x * 128;        // HG rows; samples m0/2..+63
    const int tid = threadIdx.x, lane = tid & 31, w = tid >> 5;
    const int wm = (w & 3) * 32, wn = (w >> 2) * 96;
    const __half* Ag = (MODE == 0) ? g_Xh : g_D;

    uint32_t acc[2][12][2];
#pragma unroll
    for (int a = 0; a < 2; a++)
#pragma unroll
        for (int b = 0; b < 12; b++) { acc[a][b][0] = 0u; acc[a][b][1] = 0u; }

    g_fill(sh, 0, 0, Ag, m0, tid); cp_commit();
    g_fill(sh, 1, G_BK, Ag, m0, tid); cp_commit();

#pragma unroll 1
    for (int it = 0; it < G_NIT; it++) {
        cp_wait<1>();
        __syncthreads();
        if (it + 2 < G_NIT)
            g_fill(sh, (it + 2) % 3, (it + 2) * G_BK, Ag, m0, tid);
        cp_commit();

        const __half* As = sh + (it % 3) * G_STAGE_ELEMS;
        const __half* Bs = As + 128 * 32;
#pragma unroll
        for (int kk = 0; kk < G_BK; kk += 16) {
            uint32_t af[2][4];
#pragma unroll
            for (int mt = 0; mt < 2; mt++) {
                int row = wm + mt * 16 + (lane & 15);
                int koff = kk + ((lane >> 4) << 3);
                ldsm4(af[mt][0], af[mt][1], af[mt][2], af[mt][3],
                      &As[g_off(row, koff >> 3)]);
            }
#pragma unroll
            for (int q = 0; q < 6; q++) {
                uint32_t bfr[2][2];
                int nrow = wn + q * 16 + (lane & 7) + ((lane >> 4) & 1) * 8;
                int koff = kk + (lane & 8);
                ldsm4(bfr[0][0], bfr[0][1], bfr[1][0], bfr[1][1],
                      &Bs[g_off(nrow, koff >> 3)]);
#pragma unroll
                for (int mt = 0; mt < 2; mt++) {
                    mma_h(acc[mt][2 * q + 0][0], acc[mt][2 * q + 0][1], af[mt], bfr[0]);
                    mma_h(acc[mt][2 * q + 1][0], acc[mt][2 * q + 1][1], af[mt], bfr[1]);
                }
            }
        }
    }
    cp_wait<0>();
    __syncthreads();                  // stage buffers free -> exchange

    // dump accumulators to exchange buffer [128 rows][392 stride]
    const int g = lane >> 2, c2 = (lane & 3) << 1;
#pragma unroll
    for (int mt = 0; mt < 2; mt++) {
#pragma unroll
        for (int nt = 0; nt < 12; nt++) {
            int col = wn + nt * 8 + c2;
            int r0 = wm + mt * 16 + g;
            *(uint32_t*)&sh[r0 * G_EX_STRIDE + col]       = acc[mt][nt][0];
            *(uint32_t*)&sh[(r0 + 8) * G_EX_STRIDE + col] = acc[mt][nt][1];
        }
    }
    __syncthreads();

    // inline radix-2 combine: 64 samples x 384 column-pairs
    const size_t s0 = m0 >> 1;
#pragma unroll 1
    for (int e = tid; e < 64 * 384; e += 512) {
        int sig = e >> 8;                 // e / 384? no: use div
        sig = e / 384;
        int pp = e - sig * 384;
        int k = pp * 2;
        const __half* he = sh + (2 * sig) * G_EX_STRIDE;
        const __half* ho = he + G_EX_STRIDE;
        int k1a = (k >= KDIM) ? k - KDIM : k;
        int kfa = k1a ? KDIM - k1a : 0;
        int k1b = k1a + 1;
        int kfb = KDIM - k1b;
        float2 twa = g_tw[k], twb = g_tw[k + 1];
        float va = __half2float(he[k1a]) + twa.x * __half2float(ho[k1a])
                 + twa.y * __half2float(ho[kfa]);
        float vb = __half2float(he[k1b]) + twb.x * __half2float(ho[k1b])
                 + twb.y * __half2float(ho[kfb]);
        if (MODE == 0) {
            __half2 hv;
            hv.x = __float2half(va); hv.y = __float2half(vb);
            *(__half2*)&g_Y[(s0 + sig) * CDIM + k] = hv;
        } else {
            float2 xv = *(const float2*)&xbias[(s0 + sig) * CDIM + k];
            float2 ov;
            ov.x = va * INV_NTOT + xv.x;
            ov.y = vb * INV_NTOT + xv.y;
            *(float2*)&outp[(s0 + sig) * CDIM + k] = ov;
        }
    }
}

// ---------------- fused block-diagonal MLP (R14; coalesced split-D store) ----------------
constexpr int MLP_SMEM = 196352;

__global__ void __launch_bounds__(512) mlp_kernel(const float* __restrict__ b1,
                                                  const float* __restrict__ b2) {
    extern __shared__ char smem[];
    __half* Ys  = (__half*)(smem);               // 256 x 104 (phase A / exchange)
    __half* W1s = (__half*)(smem + 53248);       // 192 x 104
    __half* W2s = (__half*)(smem);               // 192 x 200 (phase B)
    __half* O1s = (__half*)(smem + 93184);       // 256 x 200
    __half* Dbuf = O1s;                          // 256 x 96 staging (after GEMM-B)
    __half2* bias1h = (__half2*)(smem + 195584);
    __half2* bias2h = bias1h + 96;

    const int m0 = blockIdx.x * 256;
    const int blk = blockIdx.y;
    const int tid = threadIdx.x, lane = tid & 31, w = tid >> 5;
    const int wm = (w & 7) * 32, wn = (w >> 3) * 96;  // warps 0-7 real, 8-15 imag

    for (int e = tid; e < 3072; e += 512) {
        int r = e / 12, q = e % 12;
        cpa16(&Ys[r * 104 + q * 8],
              &g_Y[(size_t)(m0 + r) * CDIM + blk * 96 + q * 8]);
    }
    for (int e = tid; e < 2304; e += 512) {
        int r = e / 12, q = e % 12;
        cpa16(&W1s[r * 104 + q * 8], &g_W1T[(blk * 192 + r) * 96 + q * 8]);
    }
    cp_commit();
    if (tid < 96) {
        int cA = tid * 2;
        float va0, va1, vb0, vb1;
        if (cA < 96) {
            va0 = b1[blk * 96 + cA];       va1 = b1[blk * 96 + cA + 1];
            vb0 = b2[blk * 96 + cA];       vb1 = b2[blk * 96 + cA + 1];
        } else {
            va0 = b1[(NB + blk) * 96 + cA - 96]; va1 = b1[(NB + blk) * 96 + cA - 95];
            vb0 = b2[(NB + blk) * 96 + cA - 96]; vb1 = b2[(NB + blk) * 96 + cA - 95];
        }
        bias1h[tid] = __floats2half2_rn(va0, va1);
        bias2h[tid] = __floats2half2_rn(vb0, vb1);
    }
    cp_wait<0>();
    __syncthreads();

    const int g = lane >> 2, c2 = (lane & 3) << 1;
    const __half2 zero2 = __float2half2_rn(0.f);
    const __half2 lam2 = __float2half2_rn(LAMBDA);

    uint32_t acc[2][12][2];
#pragma unroll
    for (int a = 0; a < 2; a++)
#pragma unroll
        for (int b = 0; b < 12; b++) { acc[a][b][0] = 0u; acc[a][b][1] = 0u; }

    // ---- GEMM-A: [256,96] @ [96,192] ----
#pragma unroll
    for (int k0 = 0; k0 < 96; k0 += 16) {
        uint32_t af[2][4];
#pragma unroll
        for (int mt = 0; mt < 2; mt++)
            ldsm4(af[mt][0], af[mt][1], af[mt][2], af[mt][3],
                  &Ys[(wm + mt * 16 + (lane & 15)) * 104 + k0 + ((lane >> 4) << 3)]);
#pragma unroll
        for (int q = 0; q < 6; q++) {
            uint32_t bfr[2][2];
            int nrow = wn + q * 16 + (lane & 7) + ((lane >> 4) & 1) * 8;
            int koff = k0 + (lane & 8);
            ldsm4(bfr[0][0], bfr[0][1], bfr[1][0], bfr[1][1], &W1s[nrow * 104 + koff]);
#pragma unroll
            for (int mt = 0; mt < 2; mt++) {
                mma_h(acc[mt][2 * q + 0][0], acc[mt][2 * q + 0][1], af[mt], bfr[0]);
                mma_h(acc[mt][2 * q + 1][0], acc[mt][2 * q + 1][1], af[mt], bfr[1]);
            }
        }
    }
    __syncthreads();            // done reading Ys/W1s

    for (int e = tid; e < 4608; e += 512) {          // W2 load overlaps epilogue A
        int r = e / 24, q = e % 24;
        cpa16(&W2s[r * 200 + q * 8], &g_W2T[(blk * 192 + r) * 192 + q * 8]);
    }
    cp_commit();

#pragma unroll
    for (int mt = 0; mt < 2; mt++) {
#pragma unroll
        for (int nt = 0; nt < 12; nt++) {
            int col = wn + nt * 8 + c2;
            int r0 = wm + mt * 16 + g;
            __half2 bia = bias1h[col >> 1];
            __half2 v0 = __hmax2(__hadd2(*(__half2*)&acc[mt][nt][0], bia), zero2);
            __half2 v1 = __hmax2(__hadd2(*(__half2*)&acc[mt][nt][1], bia), zero2);
            *(__half2*)&O1s[r0 * 200 + col] = v0;
            *(__half2*)&O1s[(r0 + 8) * 200 + col] = v1;
        }
    }
    cp_wait<0>();
    __syncthreads();

    // ---- GEMM-B: [256,192] @ [192,192] ----
#pragma unroll
    for (int a = 0; a < 2; a++)
#pragma unroll
        for (int b = 0; b < 12; b++) { acc[a][b][0] = 0u; acc[a][b][1] = 0u; }

#pragma unroll
    for (int k0 = 0; k0 < 192; k0 += 16) {
        uint32_t af[2][4];
#pragma unroll
        for (int mt = 0; mt < 2; mt++)
            ldsm4(af[mt][0], af[mt][1], af[mt][2], af[mt][3],
                  &O1s[(wm + mt * 16 + (lane & 15)) * 200 + k0 + ((lane >> 4) << 3)]);
#pragma unroll
        for (int q = 0; q < 6; q++) {
            uint32_t bfr[2][2];
            int nrow = wn + q * 16 + (lane & 7) + ((lane >> 4) & 1) * 8;
            int koff = k0 + (lane & 8);
            ldsm4(bfr[0][0], bfr[0][1], bfr[1][0], bfr[1][1], &W2s[nrow * 200 + koff]);
#pragma unroll
            for (int mt = 0; mt < 2; mt++) {
                mma_h(acc[mt][2 * q + 0][0], acc[mt][2 * q + 0][1], af[mt], bfr[0]);
                mma_h(acc[mt][2 * q + 1][0], acc[mt][2 * q + 1][1], af[mt], bfr[1]);
            }
        }
    }
    __syncthreads();            // done reading O1s / W2s

    // epilogue B: bias + softshrink; imag warps export via exchange buffer (Ys)
#pragma unroll
    for (int mt = 0; mt < 2; mt++) {
#pragma unroll
        for (int nt = 0; nt < 12; nt++) {
            int col = wn + nt * 8 + c2;
            __half2 bia = bias2h[col >> 1];
#pragma unroll
            for (int j = 0; j < 2; j++) {
                __half2 v = __hadd2(*(__half2*)&acc[mt][nt][j], bia);
                __half2 t = __hmax2(__hsub2(__habs2(v), lam2), zero2);
                uint32_t s = (*(uint32_t*)&t) | ((*(uint32_t*)&v) & 0x80008000u);
                acc[mt][nt][j] = s;
            }
            if (w >= 8) {
                int r0 = wm + mt * 16 + g;
                int colL = col - 96;
                *(uint32_t*)&Ys[r0 * 104 + colL]       = acc[mt][nt][0];
                *(uint32_t*)&Ys[(r0 + 8) * 104 + colL] = acc[mt][nt][1];
            }
        }
    }
    __syncthreads();

    // real warps: d = ss(real) - ss(imag) -> Dbuf [row][De(48)|Do(48)]
    if (w < 8) {
#pragma unroll
        for (int mt = 0; mt < 2; mt++) {
#pragma unroll
            for (int nt = 0; nt < 12; nt++) {
                int col = nt * 8 + c2;
                int r0 = wm + mt * 16 + g;
                __half2 i0 = *(__half2*)&Ys[r0 * 104 + col];
                __half2 i1 = *(__half2*)&Ys[(r0 + 8) * 104 + col];
                __half2 d0 = __hsub2(*(__half2*)&acc[mt][nt][0], i0);
                __half2 d1 = __hsub2(*(__half2*)&acc[mt][nt][1], i1);
                int m = col >> 1;                 // 0..47
                Dbuf[r0 * 96 + m]            = __low2half(d0);   // De
                Dbuf[r0 * 96 + 48 + m]       = __high2half(d0);  // Do
                Dbuf[(r0 + 8) * 96 + m]      = __low2half(d1);
                Dbuf[(r0 + 8) * 96 + 48 + m] = __high2half(d1);
            }
        }
    }
    __syncthreads();

    // coalesced write: 256 rows x 12 uint4 chunks (6 De + 6 Do)
    for (int e = tid; e < 3072; e += 512) {
        int r = e / 12, q = e % 12;
        uint4 v = *(const uint4*)&Dbuf[r * 96 + q * 8];
        size_t base = (size_t)(m0 + r) * CDIM;
        if (q < 6)
            *(uint4*)&g_D[base + blk * 48 + q * 8] = v;
        else
            *(uint4*)&g_D[base + 384 + blk * 48 + (q - 6) * 8] = v;
    }
}

// ---------------- launch ----------------
extern "C" void kernel_launch(void* const* d_in, const int* in_sizes, int n_in,
                              void* d_out, int out_size) {
    const float* x  = (const float*)d_in[0];
    const float* w1 = (const float*)d_in[1];
    const float* b1 = (const float*)d_in[2];
    const float* w2 = (const float*)d_in[3];
    const float* b2 = (const float*)d_in[4];
    float* out = (float*)d_out;

    cudaFuncSetAttribute(gemm_comb<0>, cudaFuncAttributeMaxDynamicSharedMemorySize, G_SMEM_BYTES);
    cudaFuncSetAttribute(gemm_comb<1>, cudaFuncAttributeMaxDynamicSharedMemorySize, G_SMEM_BYTES);
    cudaFuncSetAttribute(mlp_kernel, cudaFuncAttributeMaxDynamicSharedMemorySize, MLP_SMEM);

    // launch order: gemm_comb<1> is the 4th launch -> ncu capture slot
    prep_all<<<PREP_BLOCKS, 256>>>(x, w1, w2);
    gemm_comb<0><<<2 * ROWS_TOTAL / 128, 512, G_SMEM_BYTES>>>(nullptr, nullptr);
    mlp_kernel<<<dim3(ROWS_TOTAL / 256, NB), 512, MLP_SMEM>>>(b1, b2);
    gemm_comb<1><<<2 * ROWS_TOTAL / 128, 512, G_SMEM_BYTES>>>(x, out);
}

// round 16
// speedup vs baseline: 1.1389x; 1.1389x over previous
#include <cuda_runtime.h>
#include <cuda_fp16.h>
#include <cstdint>

#define DINLINE __device__ __forceinline__

// ---------------- problem constants ----------------
#define ROWS_TOTAL 32768      // B*N = 8*4096
#define CDIM 768
#define KDIM 384              // radix-2 half transform
#define NB 8
#define INV_NTOT (1.0f/25165824.0f)   // 1 / (B*H*W*C)
#define LAMBDA 0.01f

// ---------------- device scratch ----------------
__device__ __half g_cas384[KDIM * KDIM];               // symmetric 384-pt cas
__device__ float2 g_tw[CDIM];                          // (cos, sin)(2πk/768)
__device__ __half g_Xh[(size_t)ROWS_TOTAL * CDIM];     // [r][xe(384)|xo(384)]
__device__ __half g_HG[(size_t)ROWS_TOTAL * CDIM];     // [2r]=He/Ge, [2r+1]=Ho/Go
__device__ __half g_Y[(size_t)ROWS_TOTAL * CDIM];      // interleaved Y (MLP input)
__device__ __half g_D[(size_t)ROWS_TOTAL * CDIM];      // [r][De(384)|Do(384)]
__device__ __half g_W1T[NB * 192 * 96];
__device__ __half g_W2T[NB * 192 * 192];

// ---------------- asm helpers ----------------
DINLINE void ldsm4(uint32_t& r0, uint32_t& r1, uint32_t& r2, uint32_t& r3, const void* p) {
    uint32_t a = (uint32_t)__cvta_generic_to_shared(p);
    asm volatile("ldmatrix.sync.aligned.m8n8.x4.shared.b16 {%0,%1,%2,%3}, [%4];"
                 : "=r"(r0), "=r"(r1), "=r"(r2), "=r"(r3) : "r"(a));
}
DINLINE void mma_h(uint32_t& c0, uint32_t& c1, const uint32_t* a, const uint32_t* b) {
    asm volatile("mma.sync.aligned.m16n8k16.row.col.f16.f16.f16.f16 "
                 "{%0,%1}, {%2,%3,%4,%5}, {%6,%7}, {%0,%1};"
                 : "+r"(c0), "+r"(c1)
                 : "r"(a[0]), "r"(a[1]), "r"(a[2]), "r"(a[3]),
                   "r"(b[0]), "r"(b[1]));
}
DINLINE void cpa16(void* smem, const void* g) {
    uint32_t a = (uint32_t)__cvta_generic_to_shared(smem);
    asm volatile("cp.async.cg.shared.global [%0], [%1], 16;" :: "r"(a), "l"(g));
}
DINLINE void cp_commit() { asm volatile("cp.async.commit_group;"); }
template<int N> DINLINE void cp_wait() { asm volatile("cp.async.wait_group %0;" :: "n"(N)); }

// ---------------- fused prep kernel ----------------
constexpr int PX_BLOCKS  = 24576;   // 6,291,456 float4 / 256
constexpr int PCAS_BLOCKS = 576;    // 384*384 / 256
constexpr int PW1_BLOCKS = 576;
constexpr int PW2_BLOCKS = 1152;
constexpr int PREP_BLOCKS = PX_BLOCKS + PCAS_BLOCKS + 1 + PW1_BLOCKS + PW2_BLOCKS;

__global__ void prep_all(const float* __restrict__ x,
                         const float* __restrict__ w1,
                         const float* __restrict__ w2) {
    int bid = blockIdx.x, tid = threadIdx.x;
    if (bid < PX_BLOCKS) {
        size_t i = ((size_t)bid * 256 + tid) * 4;
        float4 v = *(const float4*)&x[i];
        size_t r = i / CDIM;
        int c = (int)(i % CDIM);
        int m = c >> 1;
        __half2 he, hoo;
        he.x = __float2half(v.x);  he.y = __float2half(v.z);
        hoo.x = __float2half(v.y); hoo.y = __float2half(v.w);
        *(__half2*)&g_Xh[r * CDIM + m]        = he;
        *(__half2*)&g_Xh[r * CDIM + 384 + m]  = hoo;
    } else if (bid < PX_BLOCKS + PCAS_BLOCKS) {
        int idx = (bid - PX_BLOCKS) * 256 + tid;
        int i = idx / KDIM, j = idx % KDIM;
        int p = (int)(((long long)i * (long long)j) % KDIM);
        float ang = (float)p * (6.28318530717958647692f / (float)KDIM);
        g_cas384[idx] = __float2half(cosf(ang) + sinf(ang));
    } else if (bid == PX_BLOCKS + PCAS_BLOCKS) {
#pragma unroll
        for (int q = 0; q < 3; q++) {
            int k = tid + q * 256;
            float ang = (float)k * (6.28318530717958647692f / (float)CDIM);
            g_tw[k] = make_float2(cosf(ang), sinf(ang));
        }
    } else if (bid < PX_BLOCKS + PCAS_BLOCKS + 1 + PW1_BLOCKS) {
        int idx = (bid - PX_BLOCKS - PCAS_BLOCKS - 1) * 256 + tid;
        int i = idx % 96;
        int n = (idx / 96) % 192;
        int k = idx / (96 * 192);
        float v = (n < 96) ? w1[((0 * NB + k) * 96 + i) * 96 + n]
                           : w1[((1 * NB + k) * 96 + i) * 96 + (n - 96)];
        g_W1T[idx] = __float2half(v);
    } else {
        int idx = (bid - PX_BLOCKS - PCAS_BLOCKS - 1 - PW1_BLOCKS) * 256 + tid;
        int j = idx % 192;
        int c = (idx / 192) % 192;
        int k = idx / (192 * 192);
        float v;
        if (c < 96) {
            v = (j < 96) ?  w2[((0 * NB + k) * 96 + j) * 96 + c]
                         : -w2[((1 * NB + k) * 96 + (j - 96)) * 96 + c];
        } else {
            int cc = c - 96;
            v = (j < 96) ?  w2[((1 * NB + k) * 96 + j) * 96 + cc]
                         :  w2[((0 * NB + k) * 96 + (j - 96)) * 96 + cc];
        }
        g_W2T[idx] = __float2half(v);
    }
}

// ---------------- half GEMM: [65536,384] @ cas384[384,384] -> g_HG ----------------
constexpr int G_BK = 32;
constexpr int G_STAGE_ELEMS = 2 * 128 * 32;            // 16KB
constexpr int G_SMEM = 3 * G_STAGE_ELEMS * 2;          // 49152 B
constexpr int G_NIT = KDIM / G_BK;                     // 12

DINLINE uint32_t g_off(int r, int chunk) {
    return (uint32_t)(r * 32 + ((chunk ^ ((r >> 1) & 3)) << 3));
}

DINLINE void g_fill(__half* sh, int s, int k0,
                    const __half* __restrict__ Ag,
                    size_t m0, int n0, int tid) {
    __half* As = sh + s * G_STAGE_ELEMS;
    __half* Bs = As + 128 * 32;
#pragma unroll
    for (int e = tid; e < 512; e += 256) {
        int r = e >> 2, c = e & 3;
        uint32_t off = g_off(r, c);
        cpa16(&As[off], &Ag[(m0 + r) * KDIM + k0 + c * 8]);
        cpa16(&Bs[off], &g_cas384[(size_t)(n0 + r) * KDIM + k0 + c * 8]);
    }
}

template<int MODE>
__global__ void __launch_bounds__(256, 4) gemm384() {
    extern __shared__ __half sh[];
    const int n0 = blockIdx.x * 128;
    const size_t m0 = (size_t)blockIdx.y * 128;
    const int tid = threadIdx.x, lane = tid & 31, w = tid >> 5;
    const int wm = (w & 3) * 32, wn = (w >> 2) * 64;
    const __half* Ag = (MODE == 0) ? g_Xh : g_D;

    uint32_t acc[2][8][2];
#pragma unroll
    for (int a = 0; a < 2; a++)
#pragma unroll
        for (int b = 0; b < 8; b++) { acc[a][b][0] = 0u; acc[a][b][1] = 0u; }

    g_fill(sh, 0, 0, Ag, m0, n0, tid); cp_commit();
    g_fill(sh, 1, G_BK, Ag, m0, n0, tid); cp_commit();

#pragma unroll 1
    for (int it = 0; it < G_NIT; it++) {
        cp_wait<1>();
        __syncthreads();
        if (it + 2 < G_NIT)
            g_fill(sh, (it + 2) % 3, (it + 2) * G_BK, Ag, m0, n0, tid);
        cp_commit();

        const __half* As = sh + (it % 3) * G_STAGE_ELEMS;
        const __half* Bs = As + 128 * 32;
#pragma unroll
        for (int kk = 0; kk < G_BK; kk += 16) {
            uint32_t af[2][4];
#pragma unroll
            for (int mt = 0; mt < 2; mt++) {
                int row = wm + mt * 16 + (lane & 15);
                int koff = kk + ((lane >> 4) << 3);
                ldsm4(af[mt][0], af[mt][1], af[mt][2], af[mt][3],
                      &As[g_off(row, koff >> 3)]);
            }
#pragma unroll
            for (int q = 0; q < 4; q++) {
                uint32_t bfr[2][2];
                int nrow = wn + q * 16 + (lane & 7) + ((lane >> 4) & 1) * 8;
                int koff = kk + (lane & 8);
                ldsm4(bfr[0][0], bfr[0][1], bfr[1][0], bfr[1][1],
                      &Bs[g_off(nrow, koff >> 3)]);
#pragma unroll
                for (int mt = 0; mt < 2; mt++) {
                    mma_h(acc[mt][2 * q + 0][0], acc[mt][2 * q + 0][1], af[mt], bfr[0]);
                    mma_h(acc[mt][2 * q + 1][0], acc[mt][2 * q + 1][1], af[mt], bfr[1]);
                }
            }
        }
    }

    const int g = lane >> 2, c2 = (lane & 3) << 1;
#pragma unroll
    for (int mt = 0; mt < 2; mt++) {
#pragma unroll
        for (int nt = 0; nt < 8; nt++) {
            int col = n0 + wn + nt * 8 + c2;
            size_t row = m0 + wm + mt * 16 + g;
            *(uint32_t*)&g_HG[row * KDIM + col]       = acc[mt][nt][0];
            *(uint32_t*)&g_HG[(row + 8) * KDIM + col] = acc[mt][nt][1];
        }
    }
}

// ---------------- radix-2 combine 0: He/Ho -> Y (SMEM row-staged) ----------------
__global__ void __launch_bounds__(256) combine0_k() {
    __shared__ __half hs[4 * CDIM];
    const int tid = threadIdx.x;
    const size_t r0 = (size_t)blockIdx.x * 4;
    const uint4* src = (const uint4*)(g_HG + r0 * CDIM);
#pragma unroll
    for (int e = tid; e < 384; e += 256)
        ((uint4*)hs)[e] = src[e];
    __syncthreads();
#pragma unroll
    for (int e = tid * 2; e < 4 * CDIM; e += 512) {
        int rr = e / CDIM, k = e - rr * CDIM;
        const __half* he = hs + rr * CDIM;
        const __half* ho = he + KDIM;
        int k1a = (k >= KDIM) ? k - KDIM : k;
        int kfa = k1a ? KDIM - k1a : 0;
        int k1b = k1a + 1;
        int kfb = KDIM - k1b;
        float2 twa = g_tw[k], twb = g_tw[k + 1];
        float va = __half2float(he[k1a]) + twa.x * __half2float(ho[k1a])
                 + twa.y * __half2float(ho[kfa]);
        float vb = __half2float(he[k1b]) + twb.x * __half2float(ho[k1b])
                 + twb.y * __half2float(ho[kfb]);
        __half2 hv;
        hv.x = __float2half(va); hv.y = __float2half(vb);
        *(__half2*)&g_Y[(r0 + rr) * CDIM + k] = hv;
    }
}

// ---------------- radix-2 combine 1: Ge/Go -> out = acc*INV + x ----------------
__global__ void __launch_bounds__(256) combine1_k(const float* __restrict__ x,
                                                  float* __restrict__ outp) {
    __shared__ __half hs[4 * CDIM];
    const int tid = threadIdx.x;
    const size_t r0 = (size_t)blockIdx.x * 4;
    const uint4* src = (const uint4*)(g_HG + r0 * CDIM);
#pragma unroll
    for (int e = tid; e < 384; e += 256)
        ((uint4*)hs)[e] = src[e];
    __syncthreads();
#pragma unroll
    for (int e = tid * 4; e < 4 * CDIM; e += 1024) {
        int rr = e / CDIM, c = e - rr * CDIM;
        const __half* ge = hs + rr * CDIM;
        const __half* go = ge + KDIM;
        float4 xv = *(const float4*)&x[(r0 + rr) * CDIM + c];
        float o[4];
#pragma unroll
        for (int j = 0; j < 4; j++) {
            int cj = c + j;
            int c1 = (cj >= KDIM) ? cj - KDIM : cj;
            int cf = c1 ? KDIM - c1 : 0;
            float2 tw = g_tw[cj];
            o[j] = (__half2float(ge[c1]) + tw.x * __half2float(go[c1])
                  + tw.y * __half2float(go[cf])) * INV_NTOT;
        }
        float4 ov;
        ov.x = o[0] + xv.x; ov.y = o[1] + xv.y;
        ov.z = o[2] + xv.z; ov.w = o[3] + xv.w;
        *(float4*)&outp[(r0 + rr) * CDIM + c] = ov;
    }
}

// ---------------- MLP with register-resident O1 (C->A fragment identity) ----------------
// 128-row tiles, 8 warps, warp tile 16 rows x 192 cols.  SMEM phases:
//   A: Ys 128x104 (26,624) + W1s 192x104 (39,936)  -> 66,560
//   B: W2s 192x200 (76,800) overlays region 0
//   C: Dbuf 128x96 (24,576) overlays region 0
constexpr int MLP_SMEM = 77824;

__global__ void __launch_bounds__(256, 2) mlp_kernel(const float* __restrict__ b1,
                                                     const float* __restrict__ b2) {
    extern __shared__ char smem[];
    __half* Ys  = (__half*)(smem);               // 128 x 104
    __half* W1s = (__half*)(smem + 26624);       // 192 x 104
    __half* W2s = (__half*)(smem);               // 192 x 200 (phase B)
    __half* Dbuf = (__half*)(smem);              // 128 x 96 (phase C)
    __half2* bias1h = (__half2*)(smem + 76800);  // 96 pairs
    __half2* bias2h = bias1h + 96;

    const int m0 = blockIdx.x * 128;
    const int blk = blockIdx.y;
    const int tid = threadIdx.x, lane = tid & 31, w = tid >> 5;
    const int wrow = w * 16;

    // ---- phase A loads ----
#pragma unroll
    for (int e = tid; e < 1536; e += 256) {       // Y: 128 x 12 chunks
        int r = e / 12, q = e % 12;
        cpa16(&Ys[r * 104 + q * 8],
              &g_Y[(size_t)(m0 + r) * CDIM + blk * 96 + q * 8]);
    }
#pragma unroll
    for (int e = tid; e < 2304; e += 256) {       // W1: 192 x 12
        int r = e / 12, q = e % 12;
        cpa16(&W1s[r * 104 + q * 8], &g_W1T[(blk * 192 + r) * 96 + q * 8]);
    }
    cp_commit();
    if (tid < 96) {
        int cA = tid * 2;
        float va0, va1, vb0, vb1;
        if (cA < 96) {
            va0 = b1[blk * 96 + cA];       va1 = b1[blk * 96 + cA + 1];
            vb0 = b2[blk * 96 + cA];       vb1 = b2[blk * 96 + cA + 1];
        } else {
            va0 = b1[(NB + blk) * 96 + cA - 96]; va1 = b1[(NB + blk) * 96 + cA - 95];
            vb0 = b2[(NB + blk) * 96 + cA - 96]; vb1 = b2[(NB + blk) * 96 + cA - 95];
        }
        bias1h[tid] = __floats2half2_rn(va0, va1);
        bias2h[tid] = __floats2half2_rn(vb0, vb1);
    }
    cp_wait<0>();
    __syncthreads();

    const int g = lane >> 2, c2 = (lane & 3) << 1;
    const __half2 zero2 = __float2half2_rn(0.f);
    const __half2 lam2 = __float2half2_rn(LAMBDA);

    // ---- GEMM-A: [16 rows/warp, 192] @ W1 (K=96); O1 stays in registers ----
    uint32_t o1[24][2];
#pragma unroll
    for (int a = 0; a < 24; a++) { o1[a][0] = 0u; o1[a][1] = 0u; }

#pragma unroll
    for (int k0 = 0; k0 < 96; k0 += 16) {
        uint32_t af[4];
        ldsm4(af[0], af[1], af[2], af[3],
              &Ys[(wrow + (lane & 15)) * 104 + k0 + ((lane >> 4) << 3)]);
#pragma unroll
        for (int q = 0; q < 12; q++) {
            uint32_t bfr[2][2];
            int nrow = q * 16 + (lane & 7) + ((lane >> 4) & 1) * 8;
            int koff = k0 + (lane & 8);
            ldsm4(bfr[0][0], bfr[0][1], bfr[1][0], bfr[1][1], &W1s[nrow * 104 + koff]);
            mma_h(o1[2 * q + 0][0], o1[2 * q + 0][1], af, bfr[0]);
            mma_h(o1[2 * q + 1][0], o1[2 * q + 1][1], af, bfr[1]);
        }
    }
    __syncthreads();           // all warps done reading Ys/W1s

    // W2 load into overlay region (overlaps in-register epilogue A)
#pragma unroll
    for (int e = tid; e < 4608; e += 256) {       // W2: 192 x 24
        int r = e / 24, q = e % 24;
        cpa16(&W2s[r * 200 + q * 8], &g_W2T[(blk * 192 + r) * 192 + q * 8]);
    }
    cp_commit();

    // epilogue A: bias + relu in registers
#pragma unroll
    for (int nt = 0; nt < 24; nt++) {
        __half2 bia = bias1h[(nt * 8 + c2) >> 1];
#pragma unroll
        for (int j = 0; j < 2; j++) {
            __half2 v = __hmax2(__hadd2(*(__half2*)&o1[nt][j], bia), zero2);
            o1[nt][j] = *(uint32_t*)&v;
        }
    }
    cp_wait<0>();
    __syncthreads();           // W2s ready

    // ---- GEMM-B: A = o1 registers (fragment identity), B = W2s, K=192 ----
    uint32_t o2[24][2];
#pragma unroll
    for (int a = 0; a < 24; a++) { o2[a][0] = 0u; o2[a][1] = 0u; }

#pragma unroll
    for (int j = 0; j < 12; j++) {
        uint32_t af[4];
        af[0] = o1[2 * j][0];      // row g,   k 16j..16j+7
        af[1] = o1[2 * j][1];      // row g+8
        af[2] = o1[2 * j + 1][0];  // row g,   k 16j+8..16j+15
        af[3] = o1[2 * j + 1][1];  // row g+8
#pragma unroll
        for (int q = 0; q < 12; q++) {
            uint32_t bfr[2][2];
            int nrow = q * 16 + (lane & 7) + ((lane >> 4) & 1) * 8;
            int koff = j * 16 + (lane & 8);
            ldsm4(bfr[0][0], bfr[0][1], bfr[1][0], bfr[1][1], &W2s[nrow * 200 + koff]);
            mma_h(o2[2 * q + 0][0], o2[2 * q + 0][1], af, bfr[0]);
            mma_h(o2[2 * q + 1][0], o2[2 * q + 1][1], af, bfr[1]);
        }
    }
    __syncthreads();           // done reading W2s -> Dbuf overlay safe

    // epilogue B: bias + softshrink; d = ss(real) - ss(imag) (same warp!)
#pragma unroll
    for (int nt = 0; nt < 12; nt++) {
        __half2 biaR = bias2h[(nt * 8 + c2) >> 1];
        __half2 biaI = bias2h[(96 + nt * 8 + c2) >> 1];
        int m = 4 * nt + (c2 >> 1);
#pragma unroll
        for (int j = 0; j < 2; j++) {
            __half2 vR = __hadd2(*(__half2*)&o2[nt][j], biaR);
            __half2 tR = __hmax2(__hsub2(__habs2(vR), lam2), zero2);
            uint32_t sR = (*(uint32_t*)&tR) | ((*(uint32_t*)&vR) & 0x80008000u);
            __half2 vI = __hadd2(*(__half2*)&o2[nt + 12][j], biaI);
            __half2 tI = __hmax2(__hsub2(__habs2(vI), lam2), zero2);
            uint32_t sI = (*(uint32_t*)&tI) | ((*(uint32_t*)&vI) & 0x80008000u);
            __half2 d = __hsub2(*(__half2*)&sR, *(__half2*)&sI);
            int row = wrow + g + (j ? 8 : 0);
            Dbuf[row * 96 + m]      = __low2half(d);   // De
            Dbuf[row * 96 + 48 + m] = __high2half(d);  // Do
        }
    }
    __syncthreads();

    // coalesced write: 128 rows x 12 uint4 chunks (6 De + 6 Do)
#pragma unroll
    for (int e = tid; e < 1536; e += 256) {
        int r = e / 12, q = e % 12;
        uint4 v = *(const uint4*)&Dbuf[r * 96 + q * 8];
        size_t base = (size_t)(m0 + r) * CDIM;
        if (q < 6)
            *(uint4*)&g_D[base + blk * 48 + q * 8] = v;
        else
            *(uint4*)&g_D[base + 384 + blk * 48 + (q - 6) * 8] = v;
    }
}

// ---------------- launch ----------------
extern "C" void kernel_launch(void* const* d_in, const int* in_sizes, int n_in,
                              void* d_out, int out_size) {
    const float* x  = (const float*)d_in[0];
    const float* w1 = (const float*)d_in[1];
    const float* b1 = (const float*)d_in[2];
    const float* w2 = (const float*)d_in[3];
    const float* b2 = (const float*)d_in[4];
    float* out = (float*)d_out;

    cudaFuncSetAttribute(gemm384<0>, cudaFuncAttributeMaxDynamicSharedMemorySize, G_SMEM);
    cudaFuncSetAttribute(gemm384<1>, cudaFuncAttributeMaxDynamicSharedMemorySize, G_SMEM);
    cudaFuncSetAttribute(mlp_kernel, cudaFuncAttributeMaxDynamicSharedMemorySize, MLP_SMEM);

    // launch order: mlp_kernel is the 4th launch -> ncu capture slot
    prep_all<<<PREP_BLOCKS, 256>>>(x, w1, w2);
    gemm384<0><<<dim3(KDIM / 128, 2 * ROWS_TOTAL / 128), 256, G_SMEM>>>();
    combine0_k<<<ROWS_TOTAL / 4, 256>>>();
    mlp_kernel<<<dim3(ROWS_TOTAL / 128, NB), 256, MLP_SMEM>>>(b1, b2);
    gemm384<1><<<dim3(KDIM / 128, 2 * ROWS_TOTAL / 128), 256, G_SMEM>>>();
    combine1_k<<<ROWS_TOTAL / 4, 256>>>(x, out);
}

// round 17
// speedup vs baseline: 1.1790x; 1.0352x over previous
#include <cuda_runtime.h>
#include <cuda_fp16.h>
#include <cstdint>

#define DINLINE __device__ __forceinline__

// ---------------- problem constants ----------------
#define ROWS_TOTAL 32768      // B*N = 8*4096
#define CDIM 768
#define KD4 192               // radix-4 quarter transform
#define NB 8
#define INV_NTOT (1.0f/25165824.0f)   // 1 / (B*H*W*C)
#define LAMBDA 0.01f

// ---------------- device scratch ----------------
__device__ __half g_cas192[KD4 * KD4];                 // symmetric 192-pt cas
__device__ float2 g_tw[CDIM];                          // (cos,sin)(2πk/768)
__device__ __half g_Xh[(size_t)ROWS_TOTAL * CDIM];     // [4r+j][m] groups
__device__ __half g_HG[(size_t)ROWS_TOTAL * CDIM];     // [4r+j][k2] H_j / G_j
__device__ __half g_Y[(size_t)ROWS_TOTAL * CDIM];      // interleaved Y (MLP input)
__device__ __half g_D[(size_t)ROWS_TOTAL * CDIM];      // [4r+j][m] groups
__device__ __half g_W1T[NB * 192 * 96];
__device__ __half g_W2T[NB * 192 * 192];

// ---------------- asm helpers ----------------
DINLINE void ldsm4(uint32_t& r0, uint32_t& r1, uint32_t& r2, uint32_t& r3, const void* p) {
    uint32_t a = (uint32_t)__cvta_generic_to_shared(p);
    asm volatile("ldmatrix.sync.aligned.m8n8.x4.shared.b16 {%0,%1,%2,%3}, [%4];"
                 : "=r"(r0), "=r"(r1), "=r"(r2), "=r"(r3) : "r"(a));
}
DINLINE void mma_h(uint32_t& c0, uint32_t& c1, const uint32_t* a, const uint32_t* b) {
    asm volatile("mma.sync.aligned.m16n8k16.row.col.f16.f16.f16.f16 "
                 "{%0,%1}, {%2,%3,%4,%5}, {%6,%7}, {%0,%1};"
                 : "+r"(c0), "+r"(c1)
                 : "r"(a[0]), "r"(a[1]), "r"(a[2]), "r"(a[3]),
                   "r"(b[0]), "r"(b[1]));
}
DINLINE void cpa16(void* smem, const void* g) {
    uint32_t a = (uint32_t)__cvta_generic_to_shared(smem);
    asm volatile("cp.async.cg.shared.global [%0], [%1], 16;" :: "r"(a), "l"(g));
}
DINLINE void cp_commit() { asm volatile("cp.async.commit_group;"); }
template<int N> DINLINE void cp_wait() { asm volatile("cp.async.wait_group %0;" :: "n"(N)); }

// ---------------- fused prep kernel ----------------
constexpr int PX_BLOCKS  = 6144;    // 32768 rows * 48 threads / 256
constexpr int PCAS_BLOCKS = 144;    // 192*192/256
constexpr int PW1_BLOCKS = 576;
constexpr int PW2_BLOCKS = 1152;
constexpr int PREP_BLOCKS = PX_BLOCKS + PCAS_BLOCKS + 1 + PW1_BLOCKS + PW2_BLOCKS;

__global__ void prep_all(const float* __restrict__ x,
                         const float* __restrict__ w1,
                         const float* __restrict__ w2) {
    int bid = blockIdx.x, tid = threadIdx.x;
    if (bid < PX_BLOCKS) {
        // radix-4 de-interleave: thread handles sample r, m-range 4t..4t+3
        int idx = bid * 256 + tid;
        int r = idx / 48, t = idx % 48;
        const float4* xf4 = (const float4*)x;
        float4 A = xf4[(size_t)r * 192 + 4 * t + 0];   // channels 16t+0..3
        float4 Bv = xf4[(size_t)r * 192 + 4 * t + 1];
        float4 Cv = xf4[(size_t)r * 192 + 4 * t + 2];
        float4 Dv = xf4[(size_t)r * 192 + 4 * t + 3];
        float a4[4] = {A.x, A.y, A.z, A.w};
        float b4[4] = {Bv.x, Bv.y, Bv.z, Bv.w};
        float c4[4] = {Cv.x, Cv.y, Cv.z, Cv.w};
        float d4[4] = {Dv.x, Dv.y, Dv.z, Dv.w};
#pragma unroll
        for (int j = 0; j < 4; j++) {
            __half2 h0, h1;
            h0.x = __float2half(a4[j]); h0.y = __float2half(b4[j]);
            h1.x = __float2half(c4[j]); h1.y = __float2half(d4[j]);
            uint2 v = { *(uint32_t*)&h0, *(uint32_t*)&h1 };
            *(uint2*)&g_Xh[((size_t)r * 4 + j) * KD4 + 4 * t] = v;
        }
    } else if (bid < PX_BLOCKS + PCAS_BLOCKS) {
        int idx = (bid - PX_BLOCKS) * 256 + tid;
        int i = idx / KD4, j = idx % KD4;
        int p = (int)(((long long)i * (long long)j) % KD4);
        float ang = (float)p * (6.28318530717958647692f / (float)KD4);
        g_cas192[idx] = __float2half(cosf(ang) + sinf(ang));
    } else if (bid == PX_BLOCKS + PCAS_BLOCKS) {
#pragma unroll
        for (int q = 0; q < 3; q++) {
            int k = tid + q * 256;
            float ang = (float)k * (6.28318530717958647692f / (float)CDIM);
            g_tw[k] = make_float2(cosf(ang), sinf(ang));
        }
    } else if (bid < PX_BLOCKS + PCAS_BLOCKS + 1 + PW1_BLOCKS) {
        int idx = (bid - PX_BLOCKS - PCAS_BLOCKS - 1) * 256 + tid;
        int i = idx % 96;
        int n = (idx / 96) % 192;
        int k = idx / (96 * 192);
        float v = (n < 96) ? w1[((0 * NB + k) * 96 + i) * 96 + n]
                           : w1[((1 * NB + k) * 96 + i) * 96 + (n - 96)];
        g_W1T[idx] = __float2half(v);
    } else {
        int idx = (bid - PX_BLOCKS - PCAS_BLOCKS - 1 - PW1_BLOCKS) * 256 + tid;
        int j = idx % 192;
        int c = (idx / 192) % 192;
        int k = idx / (192 * 192);
        float v;
        if (c < 96) {
            v = (j < 96) ?  w2[((0 * NB + k) * 96 + j) * 96 + c]
                         : -w2[((1 * NB + k) * 96 + (j - 96)) * 96 + c];
        } else {
            int cc = c - 96;
            v = (j < 96) ?  w2[((1 * NB + k) * 96 + j) * 96 + cc]
                         :  w2[((0 * NB + k) * 96 + (j - 96)) * 96 + cc];
        }
        g_W2T[idx] = __float2half(v);
    }
}

// ---------------- quarter GEMM: [131072,192] @ cas192[192,192] -> g_HG ----------------
// Tile 128 x 192 (full N), K=192, 6 iters, fp16 acc, 3 CTAs/SM.
constexpr int G_BK = 32;
constexpr int G_A_ELEMS = 128 * 32;
constexpr int G_B_ELEMS = 192 * 32;
constexpr int G_STAGE_ELEMS = G_A_ELEMS + G_B_ELEMS;   // 10240 halves = 20KB
constexpr int G_SMEM = 3 * G_STAGE_ELEMS * 2;          // 61440 B
constexpr int G_NIT = KD4 / G_BK;                      // 6

DINLINE uint32_t g_off(int r, int chunk) {
    return (uint32_t)(r * 32 + ((chunk ^ ((r >> 1) & 3)) << 3));
}

DINLINE void g_fill(__half* sh, int s, int k0,
                    const __half* __restrict__ Ag,
                    size_t m0, int tid) {
    __half* As = sh + s * G_STAGE_ELEMS;
    __half* Bs = As + G_A_ELEMS;
#pragma unroll
    for (int e = tid; e < 512; e += 256) {             // A: 128 x 4 chunks
        int r = e >> 2, c = e & 3;
        cpa16(&As[g_off(r, c)], &Ag[(m0 + r) * KD4 + k0 + c * 8]);
    }
#pragma unroll
    for (int e = tid; e < 768; e += 256) {             // B: 192 x 4 chunks
        int r = e >> 2, c = e & 3;
        cpa16(&Bs[g_off(r, c)], &g_cas192[(size_t)r * KD4 + k0 + c * 8]);
    }
}

template<int MODE>
__global__ void __launch_bounds__(256, 3) gemm192() {
    extern __shared__ __half sh[];
    const size_t m0 = (size_t)blockIdx.x * 128;
    const int tid = threadIdx.x, lane = tid & 31, w = tid >> 5;
    const int wm = (w & 3) * 32, wn = (w >> 2) * 96;
    const __half* Ag = (MODE == 0) ? g_Xh : g_D;

    uint32_t acc[2][12][2];
#pragma unroll
    for (int a = 0; a < 2; a++)
#pragma unroll
        for (int b = 0; b < 12; b++) { acc[a][b][0] = 0u; acc[a][b][1] = 0u; }

    g_fill(sh, 0, 0, Ag, m0, tid); cp_commit();
    g_fill(sh, 1, G_BK, Ag, m0, tid); cp_commit();

#pragma unroll 1
    for (int it = 0; it < G_NIT; it++) {
        cp_wait<1>();
        __syncthreads();
        if (it + 2 < G_NIT)
            g_fill(sh, (it + 2) % 3, (it + 2) * G_BK, Ag, m0, tid);
        cp_commit();

        const __half* As = sh + (it % 3) * G_STAGE_ELEMS;
        const __half* Bs = As + G_A_ELEMS;
#pragma unroll
        for (int kk = 0; kk < G_BK; kk += 16) {
            uint32_t af[2][4];
#pragma unroll
            for (int mt = 0; mt < 2; mt++) {
                int row = wm + mt * 16 + (lane & 15);
                int koff = kk + ((lane >> 4) << 3);
                ldsm4(af[mt][0], af[mt][1], af[mt][2], af[mt][3],
                      &As[g_off(row, koff >> 3)]);
            }
#pragma unroll
            for (int q = 0; q < 6; q++) {
                uint32_t bfr[2][2];
                int nrow = wn + q * 16 + (lane & 7) + ((lane >> 4) & 1) * 8;
                int koff = kk + (lane & 8);
                ldsm4(bfr[0][0], bfr[0][1], bfr[1][0], bfr[1][1],
                      &Bs[g_off(nrow, koff >> 3)]);
#pragma unroll
                for (int mt = 0; mt < 2; mt++) {
                    mma_h(acc[mt][2 * q + 0][0], acc[mt][2 * q + 0][1], af[mt], bfr[0]);
                    mma_h(acc[mt][2 * q + 1][0], acc[mt][2 * q + 1][1], af[mt], bfr[1]);
                }
            }
        }
    }

    const int g = lane >> 2, c2 = (lane & 3) << 1;
#pragma unroll
    for (int mt = 0; mt < 2; mt++) {
#pragma unroll
        for (int nt = 0; nt < 12; nt++) {
            int col = wn + nt * 8 + c2;
            size_t row = m0 + wm + mt * 16 + g;
            *(uint32_t*)&g_HG[row * KD4 + col]       = acc[mt][nt][0];
            *(uint32_t*)&g_HG[(row + 8) * KD4 + col] = acc[mt][nt][1];
        }
    }
}

// radix-4 butterfly weights from base angle
DINLINE void tw_chain(const float2 t1, float& c2, float& s2, float& c3, float& s3) {
    c2 = t1.x * t1.x - t1.y * t1.y;
    s2 = 2.f * t1.x * t1.y;
    c3 = c2 * t1.x - s2 * t1.y;
    s3 = s2 * t1.x + c2 * t1.y;
}

DINLINE float comb4(const __half* base, int k2, int kf, float2 t1) {
    float c2, s2, c3, s3;
    tw_chain(t1, c2, s2, c3, s3);
    return __half2float(base[k2])
         + t1.x * __half2float(base[192 + k2]) + t1.y * __half2float(base[192 + kf])
         + c2   * __half2float(base[384 + k2]) + s2   * __half2float(base[384 + kf])
         + c3   * __half2float(base[576 + k2]) + s3   * __half2float(base[576 + kf]);
}

// ---------------- combine 0: H0..H3 -> Y ----------------
__global__ void __launch_bounds__(256) combine0_k() {
    __shared__ __half hs[4 * CDIM];
    const int tid = threadIdx.x;
    const size_t s0 = (size_t)blockIdx.x * 4;          // 4 samples
    const uint4* src = (const uint4*)(g_HG + s0 * 4 * KD4);
#pragma unroll
    for (int e = tid; e < 384; e += 256)
        ((uint4*)hs)[e] = src[e];
    __syncthreads();
#pragma unroll
    for (int e = tid * 2; e < 4 * CDIM; e += 512) {
        int rr = e / CDIM, k = e - rr * CDIM;          // k even
        const __half* base = hs + rr * CDIM;
        int kq = k / KD4;
        int k2a = k - kq * KD4;
        int kfa = k2a ? KD4 - k2a : 0;
        int k2b = k2a + 1, kfb = KD4 - k2b;            // k2b >= 1 always
        float va = comb4(base, k2a, kfa, g_tw[k]);
        float vb = comb4(base, k2b, kfb, g_tw[k + 1]);
        __half2 hv;
        hv.x = __float2half(va); hv.y = __float2half(vb);
        *(__half2*)&g_Y[(s0 + rr) * CDIM + k] = hv;
    }
}

// ---------------- combine 1: G0..G3 -> out = acc*INV + x ----------------
__global__ void __launch_bounds__(256) combine1_k(const float* __restrict__ x,
                                                  float* __restrict__ outp) {
    __shared__ __half hs[4 * CDIM];
    const int tid = threadIdx.x;
    const size_t s0 = (size_t)blockIdx.x * 4;
    const uint4* src = (const uint4*)(g_HG + s0 * 4 * KD4);
#pragma unroll
    for (int e = tid; e < 384; e += 256)
        ((uint4*)hs)[e] = src[e];
    __syncthreads();
#pragma unroll
    for (int e = tid * 4; e < 4 * CDIM; e += 1024) {
        int rr = e / CDIM, c = e - rr * CDIM;          // multiple of 4, no 192-crossing
        const __half* base = hs + rr * CDIM;
        float4 xv = *(const float4*)&x[(s0 + rr) * CDIM + c];
        float o[4];
#pragma unroll
        for (int j = 0; j < 4; j++) {
            int cj = c + j;
            int cq = cj / KD4;
            int c1 = cj - cq * KD4;
            int cf = c1 ? KD4 - c1 : 0;
            o[j] = comb4(base, c1, cf, g_tw[cj]) * INV_NTOT;
        }
        float4 ov;
        ov.x = o[0] + xv.x; ov.y = o[1] + xv.y;
        ov.z = o[2] + xv.z; ov.w = o[3] + xv.w;
        *(float4*)&outp[(s0 + rr) * CDIM + c] = ov;
    }
}

// ---------------- MLP with register-resident O1 (R16; 4-group D store) ----------------
constexpr int MLP_SMEM = 77824;

__global__ void __launch_bounds__(256, 2) mlp_kernel(const float* __restrict__ b1,
                                                     const float* __restrict__ b2) {
    extern __shared__ char smem[];
    __half* Ys  = (__half*)(smem);               // 128 x 104
    __half* W1s = (__half*)(smem + 26624);       // 192 x 104
    __half* W2s = (__half*)(smem);               // 192 x 200 (phase B)
    __half* Dbuf = (__half*)(smem);              // 128 x 96 (phase C)
    __half2* bias1h = (__half2*)(smem + 76800);
    __half2* bias2h = bias1h + 96;

    const int m0 = blockIdx.x * 128;
    const int blk = blockIdx.y;
    const int tid = threadIdx.x, lane = tid & 31, w = tid >> 5;
    const int wrow = w * 16;

#pragma unroll
    for (int e = tid; e < 1536; e += 256) {
        int r = e / 12, q = e % 12;
        cpa16(&Ys[r * 104 + q * 8],
              &g_Y[(size_t)(m0 + r) * CDIM + blk * 96 + q * 8]);
    }
#pragma unroll
    for (int e = tid; e < 2304; e += 256) {
        int r = e / 12, q = e % 12;
        cpa16(&W1s[r * 104 + q * 8], &g_W1T[(blk * 192 + r) * 96 + q * 8]);
    }
    cp_commit();
    if (tid < 96) {
        int cA = tid * 2;
        float va0, va1, vb0, vb1;
        if (cA < 96) {
            va0 = b1[blk * 96 + cA];       va1 = b1[blk * 96 + cA + 1];
            vb0 = b2[blk * 96 + cA];       vb1 = b2[blk * 96 + cA + 1];
        } else {
            va0 = b1[(NB + blk) * 96 + cA - 96]; va1 = b1[(NB + blk) * 96 + cA - 95];
            vb0 = b2[(NB + blk) * 96 + cA - 96]; vb1 = b2[(NB + blk) * 96 + cA - 95];
        }
        bias1h[tid] = __floats2half2_rn(va0, va1);
        bias2h[tid] = __floats2half2_rn(vb0, vb1);
    }
    cp_wait<0>();
    __syncthreads();

    const int g = lane >> 2, c2 = (lane & 3) << 1;
    const __half2 zero2 = __float2half2_rn(0.f);
    const __half2 lam2 = __float2half2_rn(LAMBDA);

    uint32_t o1[24][2];
#pragma unroll
    for (int a = 0; a < 24; a++) { o1[a][0] = 0u; o1[a][1] = 0u; }

#pragma unroll
    for (int k0 = 0; k0 < 96; k0 += 16) {
        uint32_t af[4];
        ldsm4(af[0], af[1], af[2], af[3],
              &Ys[(wrow + (lane & 15)) * 104 + k0 + ((lane >> 4) << 3)]);
#pragma unroll
        for (int q = 0; q < 12; q++) {
            uint32_t bfr[2][2];
            int nrow = q * 16 + (lane & 7) + ((lane >> 4) & 1) * 8;
            int koff = k0 + (lane & 8);
            ldsm4(bfr[0][0], bfr[0][1], bfr[1][0], bfr[1][1], &W1s[nrow * 104 + koff]);
            mma_h(o1[2 * q + 0][0], o1[2 * q + 0][1], af, bfr[0]);
            mma_h(o1[2 * q + 1][0], o1[2 * q + 1][1], af, bfr[1]);
        }
    }
    __syncthreads();

#pragma unroll
    for (int e = tid; e < 4608; e += 256) {
        int r = e / 24, q = e % 24;
        cpa16(&W2s[r * 200 + q * 8], &g_W2T[(blk * 192 + r) * 192 + q * 8]);
    }
    cp_commit();

#pragma unroll
    for (int nt = 0; nt < 24; nt++) {
        __half2 bia = bias1h[(nt * 8 + c2) >> 1];
#pragma unroll
        for (int j = 0; j < 2; j++) {
            __half2 v = __hmax2(__hadd2(*(__half2*)&o1[nt][j], bia), zero2);
            o1[nt][j] = *(uint32_t*)&v;
        }
    }
    cp_wait<0>();
    __syncthreads();

    uint32_t o2[24][2];
#pragma unroll
    for (int a = 0; a < 24; a++) { o2[a][0] = 0u; o2[a][1] = 0u; }

#pragma unroll
    for (int j = 0; j < 12; j++) {
        uint32_t af[4];
        af[0] = o1[2 * j][0];
        af[1] = o1[2 * j][1];
        af[2] = o1[2 * j + 1][0];
        af[3] = o1[2 * j + 1][1];
#pragma unroll
        for (int q = 0; q < 12; q++) {
            uint32_t bfr[2][2];
            int nrow = q * 16 + (lane & 7) + ((lane >> 4) & 1) * 8;
            int koff = j * 16 + (lane & 8);
            ldsm4(bfr[0][0], bfr[0][1], bfr[1][0], bfr[1][1], &W2s[nrow * 200 + koff]);
            mma_h(o2[2 * q + 0][0], o2[2 * q + 0][1], af, bfr[0]);
            mma_h(o2[2 * q + 1][0], o2[2 * q + 1][1], af, bfr[1]);
        }
    }
    __syncthreads();

    // epilogue B: bias + softshrink; d = ss(real)-ss(imag); 4-group Dbuf
#pragma unroll
    for (int nt = 0; nt < 12; nt++) {
        int col = nt * 8 + c2;
        __half2 biaR = bias2h[col >> 1];
        __half2 biaI = bias2h[(96 + col) >> 1];
        int ml = col >> 2;            // 0..23
        int j0 = col & 3;             // 0 or 2
#pragma unroll
        for (int j = 0; j < 2; j++) {
            __half2 vR = __hadd2(*(__half2*)&o2[nt][j], biaR);
            __half2 tR = __hmax2(__hsub2(__habs2(vR), lam2), zero2);
            uint32_t sR = (*(uint32_t*)&tR) | ((*(uint32_t*)&vR) & 0x80008000u);
            __half2 vI = __hadd2(*(__half2*)&o2[nt + 12][j], biaI);
            __half2 tI = __hmax2(__hsub2(__habs2(vI), lam2), zero2);
            uint32_t sI = (*(uint32_t*)&tI) | ((*(uint32_t*)&vI) & 0x80008000u);
            __half2 d = __hsub2(*(__half2*)&sR, *(__half2*)&sI);
            int row = wrow + g + (j ? 8 : 0);
            Dbuf[row * 96 + j0 * 24 + ml]       = __low2half(d);
            Dbuf[row * 96 + (j0 + 1) * 24 + ml] = __high2half(d);
        }
    }
    __syncthreads();

    // coalesced write: 128 rows x 4 groups x 3 uint4
#pragma unroll
    for (int e = tid; e < 1536; e += 256) {
        int r = e / 12, q = e % 12;
        int jg = q / 3, part = q % 3;
        uint4 v = *(const uint4*)&Dbuf[r * 96 + jg * 24 + part * 8];
        *(uint4*)&g_D[((size_t)(m0 + r) * 4 + jg) * KD4 + blk * 24 + part * 8] = v;
    }
}

// ---------------- launch ----------------
extern "C" void kernel_launch(void* const* d_in, const int* in_sizes, int n_in,
                              void* d_out, int out_size) {
    const float* x  = (const float*)d_in[0];
    const float* w1 = (const float*)d_in[1];
    const float* b1 = (const float*)d_in[2];
    const float* w2 = (const float*)d_in[3];
    const float* b2 = (const float*)d_in[4];
    float* out = (float*)d_out;

    cudaFuncSetAttribute(gemm192<0>, cudaFuncAttributeMaxDynamicSharedMemorySize, G_SMEM);
    cudaFuncSetAttribute(gemm192<1>, cudaFuncAttributeMaxDynamicSharedMemorySize, G_SMEM);
    cudaFuncSetAttribute(mlp_kernel, cudaFuncAttributeMaxDynamicSharedMemorySize, MLP_SMEM);

    prep_all<<<PREP_BLOCKS, 256>>>(x, w1, w2);
    gemm192<0><<<4 * ROWS_TOTAL / 128, 256, G_SMEM>>>();
    combine0_k<<<ROWS_TOTAL / 4, 256>>>();
    mlp_kernel<<<dim3(ROWS_TOTAL / 128, NB), 256, MLP_SMEM>>>(b1, b2);
    gemm192<1><<<4 * ROWS_TOTAL / 128, 256, G_SMEM>>>();
    combine1_k<<<ROWS_TOTAL / 4, 256>>>(x, out);
}